// round 12
// baseline (speedup 1.0000x reference)
#include <cuda_runtime.h>
#include <cstdint>

#define B_  512
#define T_  256
#define C_  256
#define H_  64

// Scratch (allocation-free __device__ globals).
__device__ unsigned g_Qh[B_ * T_ * H_ / 2];   // Q bf16x2-packed
__device__ unsigned g_Kh[B_ * T_ * H_ / 2];   // K bf16x2-packed
__device__ float    g_V [B_ * T_ * H_];       // V fp32
// Packed n-major [Wq|Wk] operand: [128 n][128 kwords] bf16x2 (dense, no pad).
__device__ unsigned g_Bqk[128 * 128];

__device__ __forceinline__ unsigned f2tf(float x) {
    unsigned r;
    asm("cvt.rna.tf32.f32 %0, %1;" : "=r"(r) : "f"(x));
    return r;
}
__device__ __forceinline__ unsigned pkbf(float lo, float hi) {
    unsigned r;
    asm("cvt.rn.bf16x2.f32 %0, %1, %2;" : "=r"(r) : "f"(hi), "f"(lo));
    return r;
}
__device__ __forceinline__ void mma8(float* d, const unsigned* a, const unsigned* b) {
    asm volatile(
        "mma.sync.aligned.m16n8k8.row.col.f32.tf32.tf32.f32 "
        "{%0,%1,%2,%3},{%4,%5,%6,%7},{%8,%9},{%0,%1,%2,%3};"
        : "+f"(d[0]), "+f"(d[1]), "+f"(d[2]), "+f"(d[3])
        : "r"(a[0]), "r"(a[1]), "r"(a[2]), "r"(a[3]), "r"(b[0]), "r"(b[1]));
}
__device__ __forceinline__ void mma16(float* d, const unsigned* a, const unsigned* b) {
    asm volatile(
        "mma.sync.aligned.m16n8k16.row.col.f32.bf16.bf16.f32 "
        "{%0,%1,%2,%3},{%4,%5,%6,%7},{%8,%9},{%0,%1,%2,%3};"
        : "+f"(d[0]), "+f"(d[1]), "+f"(d[2]), "+f"(d[3])
        : "r"(a[0]), "r"(a[1]), "r"(a[2]), "r"(a[3]), "r"(b[0]), "r"(b[1]));
}
__device__ __forceinline__ void ldsm4(unsigned& r0, unsigned& r1, unsigned& r2, unsigned& r3,
                                      unsigned saddr) {
    asm volatile("ldmatrix.sync.aligned.m8n8.x4.shared.b16 {%0,%1,%2,%3}, [%4];"
                 : "=r"(r0), "=r"(r1), "=r"(r2), "=r"(r3) : "r"(saddr));
}
__device__ __forceinline__ unsigned scvta(const void* p) {
    return (unsigned)__cvta_generic_to_shared(p);
}
__device__ __forceinline__ void cpa16(unsigned daddr, const void* src) {
    asm volatile("cp.async.cg.shared.global [%0], [%1], 16;" :: "r"(daddr), "l"(src));
}
__device__ __forceinline__ void cpa_commit() { asm volatile("cp.async.commit_group;"); }
__device__ __forceinline__ void cpa_wait0()  { asm volatile("cp.async.wait_group 0;"); }

// L2 evict_last via cache-policy operand (legal at any store width on sm_100,
// unlike the bare .L2::evict_last qualifier which ptxas restricts to 32B).
__device__ __forceinline__ uint64_t mkpol_el() {
    uint64_t p;
    asm("createpolicy.fractional.L2::evict_last.b64 %0, 1.0;" : "=l"(p));
    return p;
}
__device__ __forceinline__ void stg32_el(unsigned* p, unsigned v, uint64_t pol) {
    asm volatile("st.global.L2::cache_hint.b32 [%0], %1, %2;"
                 :: "l"(p), "r"(v), "l"(pol) : "memory");
}
__device__ __forceinline__ void stg64_el(float* p, float2 v, uint64_t pol) {
    asm volatile("st.global.L2::cache_hint.v2.f32 [%0], {%1,%2}, %3;"
                 :: "l"(p), "f"(v.x), "f"(v.y), "l"(pol) : "memory");
}

// ---------------------------------------------------------------------------
// Kernel 0: prep. Pack [Wq|Wk] into n-major bf16x2.
// ---------------------------------------------------------------------------
__global__ void prep_kernel(const float* __restrict__ Wq,
                            const float* __restrict__ Wk)
{
    int idx = blockIdx.x * 256 + threadIdx.x;   // 0..16383
    int n  = idx >> 7;
    int kw = idx & 127;
    int nc = n & 63;
    const float* W = (n < 64) ? Wq : Wk;
    g_Bqk[idx] = pkbf(W[(2 * kw) * 64 + nc], W[(2 * kw + 1) * 64 + nc]);
}

// ---------------------------------------------------------------------------
// Kernel 1: projections (R10-proven compute; epilogues evict_last-hinted).
// ---------------------------------------------------------------------------
#define QK_BW 132
#define QK_B_WORDS (128 * QK_BW)           // 16896
#define QK_A_WORDS (2 * 128 * 20)          // 5120
#define QKV_SMEM_BYTES ((QK_B_WORDS + QK_A_WORDS) * 4)   // 88064

__global__ __launch_bounds__(256, 2) void qkv_kernel(
    const float* __restrict__ x,
    const float* __restrict__ Wv)
{
    extern __shared__ unsigned qsm[];

    const int tid  = threadIdx.x;
    const int lane = tid & 31;
    const int warp = tid >> 5;
    const int wm   = warp >> 1;
    const int wn   = warp & 1;
    const int qr   = lane >> 2;
    const int j    = lane & 3;
    const long rowbase = (long)blockIdx.y * 128;

    if (blockIdx.x == 0) {
        // ================= QK merged bf16 path =================
        unsigned* Bf = qsm;                    // [128][132]
        unsigned* Aw = qsm + QK_B_WORDS;       // [2][128][20]
        const unsigned sB = scvta(Bf), sA = scvta(Aw);

        #pragma unroll
        for (int i = 0; i < 16; i++) {
            int q = tid + i * 256;             // 0..4095
            int row = q >> 5, c4 = q & 31;
            cpa16(sB + (row * QK_BW + c4 * 4) * 4, g_Bqk + row * 128 + c4 * 4);
        }
        cpa_commit();

        const int ar_ = tid >> 3, ac4_ = tid & 7;
        const int aRow  = (lane & 7) + ((lane >> 3) & 1) * 8;
        const int aHalf = (lane >> 4) & 1;
        const int bRow  = (lane & 7) + ((lane >> 4) & 1) * 8;
        const int bHalf = (lane >> 3) & 1;

        float4 ra[4];
        #pragma unroll
        for (int i = 0; i < 4; i++)
            ra[i] = *(const float4*)(x + (rowbase + ar_ + i * 32) * 256 + ac4_ * 4);

        float acc[2][8][4];
        #pragma unroll
        for (int mt = 0; mt < 2; mt++)
            #pragma unroll
            for (int nt = 0; nt < 8; nt++)
                #pragma unroll
                for (int c = 0; c < 4; c++) acc[mt][nt][c] = 0.f;

        for (int c = 0; c < 8; c++) {
            unsigned* As = Aw + (c & 1) * 128 * 20;
            #pragma unroll
            for (int i = 0; i < 4; i++) {
                unsigned* p = As + (ar_ + i * 32) * 20 + ac4_ * 2;
                p[0] = pkbf(ra[i].x, ra[i].y);
                p[1] = pkbf(ra[i].z, ra[i].w);
            }
            if (c < 7) {
                const int kn = (c + 1) * 32;
                #pragma unroll
                for (int i = 0; i < 4; i++)
                    ra[i] = *(const float4*)(x + (rowbase + ar_ + i * 32) * 256 + kn + ac4_ * 4);
            }
            if (c == 0) cpa_wait0();
            __syncthreads();

            const unsigned aBuf = sA + (c & 1) * 128 * 20 * 4;
            #pragma unroll
            for (int s = 0; s < 2; s++) {
                unsigned a[2][4], b[8][2];
                #pragma unroll
                for (int mt = 0; mt < 2; mt++)
                    ldsm4(a[mt][0], a[mt][1], a[mt][2], a[mt][3],
                          aBuf + ((wm * 32 + mt * 16 + aRow) * 20 + s * 8 + aHalf * 4) * 4);
                #pragma unroll
                for (int p = 0; p < 4; p++)
                    ldsm4(b[2 * p][0], b[2 * p][1], b[2 * p + 1][0], b[2 * p + 1][1],
                          sB + ((wn * 64 + p * 16 + bRow) * QK_BW + c * 16 + s * 8 + bHalf * 4) * 4);
                #pragma unroll
                for (int mt = 0; mt < 2; mt++)
                    #pragma unroll
                    for (int nt = 0; nt < 8; nt++)
                        mma16(acc[mt][nt], a[mt], b[nt]);
            }
        }

        const uint64_t pol = mkpol_el();
        unsigned* outw = wn ? g_Kh : g_Qh;
        #pragma unroll
        for (int mt = 0; mt < 2; mt++) {
            long r0 = rowbase + wm * 32 + mt * 16 + qr;
            #pragma unroll
            for (int nt = 0; nt < 8; nt++) {
                int widx = nt * 4 + j;
                stg32_el(outw + r0 * 32 + widx,       pkbf(acc[mt][nt][0], acc[mt][nt][1]), pol);
                stg32_el(outw + (r0 + 8) * 32 + widx, pkbf(acc[mt][nt][2], acc[mt][nt][3]), pol);
            }
        }
    } else {
        // ================= V tf32 path (proven R5) =================
        unsigned* AsBase = qsm;                 // [2][128][36]
        unsigned* BsBase = qsm + 2 * 128 * 36;  // [2][32][72]

        const int ar_ = tid >> 3, ac4_ = tid & 7;
        const int br_ = tid >> 4, bc4_ = tid & 15;

        float4 ra[4], rb[2];
        #pragma unroll
        for (int i = 0; i < 4; i++)
            ra[i] = *(const float4*)(x + (rowbase + ar_ + i * 32) * 256 + ac4_ * 4);
        #pragma unroll
        for (int i = 0; i < 2; i++)
            rb[i] = *(const float4*)(Wv + (br_ + i * 16) * 64 + bc4_ * 4);

        float acc[2][4][4];
        #pragma unroll
        for (int mt = 0; mt < 2; mt++)
            #pragma unroll
            for (int nt = 0; nt < 4; nt++)
                #pragma unroll
                for (int c = 0; c < 4; c++) acc[mt][nt][c] = 0.f;

        for (int k0 = 0; k0 < 8; k0++) {
            unsigned* As = AsBase + (k0 & 1) * 128 * 36;
            unsigned* Bs = BsBase + (k0 & 1) * 32 * 72;

            #pragma unroll
            for (int i = 0; i < 4; i++) {
                unsigned* p = As + (ar_ + i * 32) * 36 + ac4_ * 4;
                p[0] = f2tf(ra[i].x); p[1] = f2tf(ra[i].y);
                p[2] = f2tf(ra[i].z); p[3] = f2tf(ra[i].w);
            }
            #pragma unroll
            for (int i = 0; i < 2; i++) {
                unsigned* p = Bs + (br_ + i * 16) * 72 + bc4_ * 4;
                p[0] = f2tf(rb[i].x); p[1] = f2tf(rb[i].y);
                p[2] = f2tf(rb[i].z); p[3] = f2tf(rb[i].w);
            }
            if (k0 < 7) {
                const int kn = (k0 + 1) * 32;
                #pragma unroll
                for (int i = 0; i < 4; i++)
                    ra[i] = *(const float4*)(x + (rowbase + ar_ + i * 32) * 256 + kn + ac4_ * 4);
                #pragma unroll
                for (int i = 0; i < 2; i++)
                    rb[i] = *(const float4*)(Wv + (kn + br_ + i * 16) * 64 + bc4_ * 4);
            }
            __syncthreads();

            #pragma unroll
            for (int kk = 0; kk < 4; kk++) {
                unsigned a[2][4], b[4][2];
                const int ar = wm * 32 + qr;
                const int ac = kk * 8 + j;
                #pragma unroll
                for (int mt = 0; mt < 2; mt++) {
                    a[mt][0] = As[(ar + mt * 16) * 36 + ac];
                    a[mt][1] = As[(ar + mt * 16 + 8) * 36 + ac];
                    a[mt][2] = As[(ar + mt * 16) * 36 + ac + 4];
                    a[mt][3] = As[(ar + mt * 16 + 8) * 36 + ac + 4];
                }
                const int bk = kk * 8 + j;
                #pragma unroll
                for (int nt = 0; nt < 4; nt++) {
                    const int bn = wn * 32 + nt * 8 + qr;
                    b[nt][0] = Bs[bk * 72 + bn];
                    b[nt][1] = Bs[(bk + 4) * 72 + bn];
                }
                #pragma unroll
                for (int mt = 0; mt < 2; mt++)
                    #pragma unroll
                    for (int nt = 0; nt < 4; nt++)
                        mma8(acc[mt][nt], a[mt], b[nt]);
            }
        }

        const uint64_t pol = mkpol_el();
        #pragma unroll
        for (int mt = 0; mt < 2; mt++) {
            long r0 = rowbase + wm * 32 + mt * 16 + qr;
            #pragma unroll
            for (int nt = 0; nt < 4; nt++) {
                int cc = wn * 32 + nt * 8 + 2 * j;
                stg64_el(g_V + r0 * 64 + cc,       make_float2(acc[mt][nt][0], acc[mt][nt][1]), pol);
                stg64_el(g_V + (r0 + 8) * 64 + cc, make_float2(acc[mt][nt][2], acc[mt][nt][3]), pol);
            }
        }
    }
}

// ---------------------------------------------------------------------------
// Kernel 2: fused causal attention. grid (512, 2): CTA (b, h); each warp owns
// ONE 16-row tile. h=0 -> tiles {0..3, 12..15}; h=1 -> tiles {4..11}. Both
// CTA-halves stage the full K,V (2nd read is an L2 hit given evict_last
// intermediates). 1024 CTAs -> 3.5 waves of outstanding loads vs 1.7.
// ---------------------------------------------------------------------------
#define KW_ 36
#define VW_ 72
#define ATTN_SMEM_BYTES ((256 * KW_ + 256 * VW_) * 4)

__global__ __launch_bounds__(256, 2) void attn_kernel(float* __restrict__ out)
{
    extern __shared__ unsigned sm[];
    unsigned* sK = sm;
    unsigned* sV = sm + 256 * KW_;
    const unsigned sKb = scvta(sK);

    const int tid  = threadIdx.x;
    const int lane = tid & 31;
    const int warp = tid >> 5;
    const int j    = lane & 3;
    const int qr   = lane >> 2;

    const int bRow  = (lane & 7) + ((lane >> 4) & 1) * 8;
    const int bHalf = (lane >> 3) & 1;

    const int b = blockIdx.x;
    const int h = blockIdx.y;
    const unsigned* Qw = g_Qh + (long)b * T_ * H_ / 2;
    const unsigned* Kw = g_Kh + (long)b * T_ * H_ / 2;
    const float*    Vg = g_V  + (long)b * T_ * H_;
    float* ob = out + (long)b * T_ * H_;

    #pragma unroll
    for (int i = 0; i < 8; i++) {
        int idx = tid + i * 256;
        int r = idx >> 3, c4 = idx & 7;
        uint4 kw = *(const uint4*)(Kw + r * 32 + c4 * 4);
        sK[r * KW_ + c4 * 4 + 0] = kw.x;
        sK[r * KW_ + c4 * 4 + 1] = kw.y;
        sK[r * KW_ + c4 * 4 + 2] = kw.z;
        sK[r * KW_ + c4 * 4 + 3] = kw.w;
    }
    #pragma unroll
    for (int i = 0; i < 16; i++) {
        int idx = tid + i * 256;
        int r = idx >> 4, c4 = idx & 15;
        float4 vv = *(const float4*)(Vg + r * 64 + c4 * 4);
        sV[r * VW_ + c4 * 4 + 0] = f2tf(vv.x);
        sV[r * VW_ + c4 * 4 + 1] = f2tf(vv.y);
        sV[r * VW_ + c4 * 4 + 2] = f2tf(vv.z);
        sV[r * VW_ + c4 * 4 + 3] = f2tf(vv.w);
    }
    __syncthreads();

    // One tile per warp; balanced: h=0 -> {0..3,12..15} (36 units), h=1 -> {4..11} (36).
    const int m  = h ? (warp + 4) : (warp < 4 ? warp : warp + 8);
    const int t0 = m * 16;

    unsigned aq[4][4];
    {
        const int r = t0 + qr;
        #pragma unroll
        for (int st = 0; st < 4; st++) {
            aq[st][0] = Qw[r * 32 + st * 8 + j];
            aq[st][1] = Qw[(r + 8) * 32 + st * 8 + j];
            aq[st][2] = Qw[r * 32 + st * 8 + j + 4];
            aq[st][3] = Qw[(r + 8) * 32 + st * 8 + j + 4];
        }
    }

    float o[8][4];
    #pragma unroll
    for (int nt = 0; nt < 8; nt++)
        #pragma unroll
        for (int c = 0; c < 4; c++) o[nt][c] = 0.f;
    float rs[2] = {0.f, 0.f};

    const int nb = m / 2 + 1;
    for (int sb = 0; sb < nb; sb++) {
        const int s0 = sb * 32;

        float sacc[4][4];
        #pragma unroll
        for (int nt = 0; nt < 4; nt++)
            #pragma unroll
            for (int c = 0; c < 4; c++) sacc[nt][c] = 0.f;

        #pragma unroll
        for (int st = 0; st < 4; st++) {
            unsigned bk[4][2];
            #pragma unroll
            for (int p = 0; p < 2; p++) {
                unsigned addr = sKb +
                    ((s0 + p * 16 + bRow) * KW_ + st * 8 + bHalf * 4) * 4;
                ldsm4(bk[2 * p][0], bk[2 * p][1], bk[2 * p + 1][0], bk[2 * p + 1][1], addr);
            }
            #pragma unroll
            for (int nt = 0; nt < 4; nt++)
                mma16(sacc[nt], aq[st], bk[nt]);
        }

        unsigned ap[4][4];
        const int tlo = t0 + qr, thi = tlo + 8;
        const int srcA = (lane & ~3) | (j >> 1);
        const int srcB = srcA + 2;
        const bool odd = (j & 1);
        #pragma unroll
        for (int nt = 0; nt < 4; nt++) {
            const int clo = s0 + nt * 8 + 2 * j;
            float pe0 = (clo     <= tlo) ? __expf(sacc[nt][0] * 0.0625f) : 0.f;
            float pe1 = (clo + 1 <= tlo) ? __expf(sacc[nt][1] * 0.0625f) : 0.f;
            float pe2 = (clo     <= thi) ? __expf(sacc[nt][2] * 0.0625f) : 0.f;
            float pe3 = (clo + 1 <= thi) ? __expf(sacc[nt][3] * 0.0625f) : 0.f;
            rs[0] += pe0 + pe1;
            rs[1] += pe2 + pe3;
            float g0 = __shfl_sync(0xffffffffu, pe0, srcA);
            float g1 = __shfl_sync(0xffffffffu, pe1, srcA);
            float h0 = __shfl_sync(0xffffffffu, pe0, srcB);
            float h1 = __shfl_sync(0xffffffffu, pe1, srcB);
            float g2 = __shfl_sync(0xffffffffu, pe2, srcA);
            float g3 = __shfl_sync(0xffffffffu, pe3, srcA);
            float h2 = __shfl_sync(0xffffffffu, pe2, srcB);
            float h3 = __shfl_sync(0xffffffffu, pe3, srcB);
            ap[nt][0] = f2tf(odd ? g1 : g0);
            ap[nt][1] = f2tf(odd ? g3 : g2);
            ap[nt][2] = f2tf(odd ? h1 : h0);
            ap[nt][3] = f2tf(odd ? h3 : h2);
        }

        #pragma unroll
        for (int kt = 0; kt < 4; kt++) {
            unsigned bv[8][2];
            const int sv = s0 + kt * 8 + j;
            #pragma unroll
            for (int nt = 0; nt < 8; nt++) {
                const int hh = nt * 8 + qr;
                bv[nt][0] = sV[sv * VW_ + hh];
                bv[nt][1] = sV[(sv + 4) * VW_ + hh];
            }
            #pragma unroll
            for (int nt = 0; nt < 8; nt++)
                mma8(o[nt], ap[kt], bv[nt]);
        }
    }

    #pragma unroll
    for (int h2 = 0; h2 < 2; h2++) {
        float r = rs[h2];
        r += __shfl_xor_sync(0xffffffffu, r, 1);
        r += __shfl_xor_sync(0xffffffffu, r, 2);
        rs[h2] = 1.f / r;
    }

    const int r = t0 + qr;
    #pragma unroll
    for (int nt = 0; nt < 8; nt++) {
        const int cc = nt * 8 + 2 * j;
        *(float2*)(ob + r * 64 + cc) =
            make_float2(o[nt][0] * rs[0], o[nt][1] * rs[0]);
        *(float2*)(ob + (r + 8) * 64 + cc) =
            make_float2(o[nt][2] * rs[1], o[nt][3] * rs[1]);
    }
}

// ---------------------------------------------------------------------------
extern "C" void kernel_launch(void* const* d_in, const int* in_sizes, int n_in,
                              void* d_out, int out_size)
{
    const float* x  = (const float*)d_in[0];
    const float* Wq = (const float*)d_in[1];
    const float* Wk = (const float*)d_in[2];
    const float* Wv = (const float*)d_in[3];
    float* out = (float*)d_out;

    (void)in_sizes; (void)n_in; (void)out_size;

    cudaFuncSetAttribute(qkv_kernel, cudaFuncAttributeMaxDynamicSharedMemorySize,
                         QKV_SMEM_BYTES);
    cudaFuncSetAttribute(attn_kernel, cudaFuncAttributeMaxDynamicSharedMemorySize,
                         ATTN_SMEM_BYTES);

    prep_kernel<<<64, 256>>>(Wq, Wk);
    qkv_kernel<<<dim3(2, (B_ * T_) / 128), 256, QKV_SMEM_BYTES>>>(x, Wv);
    attn_kernel<<<dim3(B_, 2), 256, ATTN_SMEM_BYTES>>>(out);
}

// round 14
// speedup vs baseline: 1.0587x; 1.0587x over previous
#include <cuda_runtime.h>
#include <cstdint>

#define B_  512
#define T_  256
#define C_  256
#define H_  64

// Scratch (allocation-free __device__ globals).
__device__ unsigned g_Qh[B_ * T_ * H_ / 2];   // Q bf16x2-packed
__device__ unsigned g_Kh[B_ * T_ * H_ / 2];   // K bf16x2-packed
__device__ float    g_V [B_ * T_ * H_];       // V fp32, PRE-ROUNDED to tf32 bits
// Packed n-major [Wq|Wk] operand: [128 n][128 kwords] bf16x2 (dense, no pad).
__device__ unsigned g_Bqk[128 * 128];

__device__ __forceinline__ unsigned f2tf(float x) {
    unsigned r;
    asm("cvt.rna.tf32.f32 %0, %1;" : "=r"(r) : "f"(x));
    return r;
}
__device__ __forceinline__ unsigned pkbf(float lo, float hi) {
    unsigned r;
    asm("cvt.rn.bf16x2.f32 %0, %1, %2;" : "=r"(r) : "f"(hi), "f"(lo));
    return r;
}
__device__ __forceinline__ void mma8(float* d, const unsigned* a, const unsigned* b) {
    asm volatile(
        "mma.sync.aligned.m16n8k8.row.col.f32.tf32.tf32.f32 "
        "{%0,%1,%2,%3},{%4,%5,%6,%7},{%8,%9},{%0,%1,%2,%3};"
        : "+f"(d[0]), "+f"(d[1]), "+f"(d[2]), "+f"(d[3])
        : "r"(a[0]), "r"(a[1]), "r"(a[2]), "r"(a[3]), "r"(b[0]), "r"(b[1]));
}
__device__ __forceinline__ void mma16(float* d, const unsigned* a, const unsigned* b) {
    asm volatile(
        "mma.sync.aligned.m16n8k16.row.col.f32.bf16.bf16.f32 "
        "{%0,%1,%2,%3},{%4,%5,%6,%7},{%8,%9},{%0,%1,%2,%3};"
        : "+f"(d[0]), "+f"(d[1]), "+f"(d[2]), "+f"(d[3])
        : "r"(a[0]), "r"(a[1]), "r"(a[2]), "r"(a[3]), "r"(b[0]), "r"(b[1]));
}
__device__ __forceinline__ void ldsm4(unsigned& r0, unsigned& r1, unsigned& r2, unsigned& r3,
                                      unsigned saddr) {
    asm volatile("ldmatrix.sync.aligned.m8n8.x4.shared.b16 {%0,%1,%2,%3}, [%4];"
                 : "=r"(r0), "=r"(r1), "=r"(r2), "=r"(r3) : "r"(saddr));
}
__device__ __forceinline__ unsigned scvta(const void* p) {
    return (unsigned)__cvta_generic_to_shared(p);
}
__device__ __forceinline__ void cpa16(unsigned daddr, const void* src) {
    asm volatile("cp.async.cg.shared.global [%0], [%1], 16;" :: "r"(daddr), "l"(src));
}
__device__ __forceinline__ void cpa_commit() { asm volatile("cp.async.commit_group;"); }
__device__ __forceinline__ void cpa_wait0()  { asm volatile("cp.async.wait_group 0;"); }

// ---------------------------------------------------------------------------
// Kernel 0: prep. Pack [Wq|Wk] into n-major bf16x2.
// ---------------------------------------------------------------------------
__global__ void prep_kernel(const float* __restrict__ Wq,
                            const float* __restrict__ Wk)
{
    int idx = blockIdx.x * 256 + threadIdx.x;   // 0..16383
    int n  = idx >> 7;
    int kw = idx & 127;
    int nc = n & 63;
    const float* W = (n < 64) ? Wq : Wk;
    g_Bqk[idx] = pkbf(W[(2 * kw) * 64 + nc], W[(2 * kw + 1) * 64 + nc]);
}

// ---------------------------------------------------------------------------
// Kernel 1: projections (R10-proven). grid (2, 1024).
//  which=0: QK merged bf16 GEMM (B resident via cp.async; ldmatrix frags).
//  which=1: V tf32 GEMM; epilogue stores tf32-ROUNDED bits (moves the f2tf
//           that attn used to do at staging -> bit-identical results, and
//           lets attn stage V with raw cp.async copies).
// ---------------------------------------------------------------------------
#define QK_BW 132
#define QK_B_WORDS (128 * QK_BW)           // 16896
#define QK_A_WORDS (2 * 128 * 20)          // 5120
#define QKV_SMEM_BYTES ((QK_B_WORDS + QK_A_WORDS) * 4)   // 88064

__global__ __launch_bounds__(256, 2) void qkv_kernel(
    const float* __restrict__ x,
    const float* __restrict__ Wv)
{
    extern __shared__ unsigned qsm[];

    const int tid  = threadIdx.x;
    const int lane = tid & 31;
    const int warp = tid >> 5;
    const int wm   = warp >> 1;
    const int wn   = warp & 1;
    const int qr   = lane >> 2;
    const int j    = lane & 3;
    const long rowbase = (long)blockIdx.y * 128;

    if (blockIdx.x == 0) {
        // ================= QK merged bf16 path =================
        unsigned* Bf = qsm;                    // [128][132]
        unsigned* Aw = qsm + QK_B_WORDS;       // [2][128][20]
        const unsigned sB = scvta(Bf), sA = scvta(Aw);

        #pragma unroll
        for (int i = 0; i < 16; i++) {
            int q = tid + i * 256;             // 0..4095
            int row = q >> 5, c4 = q & 31;
            cpa16(sB + (row * QK_BW + c4 * 4) * 4, g_Bqk + row * 128 + c4 * 4);
        }
        cpa_commit();

        const int ar_ = tid >> 3, ac4_ = tid & 7;
        const int aRow  = (lane & 7) + ((lane >> 3) & 1) * 8;
        const int aHalf = (lane >> 4) & 1;
        const int bRow  = (lane & 7) + ((lane >> 4) & 1) * 8;
        const int bHalf = (lane >> 3) & 1;

        float4 ra[4];
        #pragma unroll
        for (int i = 0; i < 4; i++)
            ra[i] = *(const float4*)(x + (rowbase + ar_ + i * 32) * 256 + ac4_ * 4);

        float acc[2][8][4];
        #pragma unroll
        for (int mt = 0; mt < 2; mt++)
            #pragma unroll
            for (int nt = 0; nt < 8; nt++)
                #pragma unroll
                for (int c = 0; c < 4; c++) acc[mt][nt][c] = 0.f;

        for (int c = 0; c < 8; c++) {
            unsigned* As = Aw + (c & 1) * 128 * 20;
            #pragma unroll
            for (int i = 0; i < 4; i++) {
                unsigned* p = As + (ar_ + i * 32) * 20 + ac4_ * 2;
                p[0] = pkbf(ra[i].x, ra[i].y);
                p[1] = pkbf(ra[i].z, ra[i].w);
            }
            if (c < 7) {
                const int kn = (c + 1) * 32;
                #pragma unroll
                for (int i = 0; i < 4; i++)
                    ra[i] = *(const float4*)(x + (rowbase + ar_ + i * 32) * 256 + kn + ac4_ * 4);
            }
            if (c == 0) cpa_wait0();
            __syncthreads();

            const unsigned aBuf = sA + (c & 1) * 128 * 20 * 4;
            #pragma unroll
            for (int s = 0; s < 2; s++) {
                unsigned a[2][4], b[8][2];
                #pragma unroll
                for (int mt = 0; mt < 2; mt++)
                    ldsm4(a[mt][0], a[mt][1], a[mt][2], a[mt][3],
                          aBuf + ((wm * 32 + mt * 16 + aRow) * 20 + s * 8 + aHalf * 4) * 4);
                #pragma unroll
                for (int p = 0; p < 4; p++)
                    ldsm4(b[2 * p][0], b[2 * p][1], b[2 * p + 1][0], b[2 * p + 1][1],
                          sB + ((wn * 64 + p * 16 + bRow) * QK_BW + c * 16 + s * 8 + bHalf * 4) * 4);
                #pragma unroll
                for (int mt = 0; mt < 2; mt++)
                    #pragma unroll
                    for (int nt = 0; nt < 8; nt++)
                        mma16(acc[mt][nt], a[mt], b[nt]);
            }
        }

        unsigned* outw = wn ? g_Kh : g_Qh;
        #pragma unroll
        for (int mt = 0; mt < 2; mt++) {
            long r0 = rowbase + wm * 32 + mt * 16 + qr;
            #pragma unroll
            for (int nt = 0; nt < 8; nt++) {
                int widx = nt * 4 + j;
                outw[r0 * 32 + widx]       = pkbf(acc[mt][nt][0], acc[mt][nt][1]);
                outw[(r0 + 8) * 32 + widx] = pkbf(acc[mt][nt][2], acc[mt][nt][3]);
            }
        }
    } else {
        // ================= V tf32 path (proven R5) =================
        unsigned* AsBase = qsm;                 // [2][128][36]
        unsigned* BsBase = qsm + 2 * 128 * 36;  // [2][32][72]

        const int ar_ = tid >> 3, ac4_ = tid & 7;
        const int br_ = tid >> 4, bc4_ = tid & 15;

        float4 ra[4], rb[2];
        #pragma unroll
        for (int i = 0; i < 4; i++)
            ra[i] = *(const float4*)(x + (rowbase + ar_ + i * 32) * 256 + ac4_ * 4);
        #pragma unroll
        for (int i = 0; i < 2; i++)
            rb[i] = *(const float4*)(Wv + (br_ + i * 16) * 64 + bc4_ * 4);

        float acc[2][4][4];
        #pragma unroll
        for (int mt = 0; mt < 2; mt++)
            #pragma unroll
            for (int nt = 0; nt < 4; nt++)
                #pragma unroll
                for (int c = 0; c < 4; c++) acc[mt][nt][c] = 0.f;

        for (int k0 = 0; k0 < 8; k0++) {
            unsigned* As = AsBase + (k0 & 1) * 128 * 36;
            unsigned* Bs = BsBase + (k0 & 1) * 32 * 72;

            #pragma unroll
            for (int i = 0; i < 4; i++) {
                unsigned* p = As + (ar_ + i * 32) * 36 + ac4_ * 4;
                p[0] = f2tf(ra[i].x); p[1] = f2tf(ra[i].y);
                p[2] = f2tf(ra[i].z); p[3] = f2tf(ra[i].w);
            }
            #pragma unroll
            for (int i = 0; i < 2; i++) {
                unsigned* p = Bs + (br_ + i * 16) * 72 + bc4_ * 4;
                p[0] = f2tf(rb[i].x); p[1] = f2tf(rb[i].y);
                p[2] = f2tf(rb[i].z); p[3] = f2tf(rb[i].w);
            }
            if (k0 < 7) {
                const int kn = (k0 + 1) * 32;
                #pragma unroll
                for (int i = 0; i < 4; i++)
                    ra[i] = *(const float4*)(x + (rowbase + ar_ + i * 32) * 256 + kn + ac4_ * 4);
                #pragma unroll
                for (int i = 0; i < 2; i++)
                    rb[i] = *(const float4*)(Wv + (kn + br_ + i * 16) * 64 + bc4_ * 4);
            }
            __syncthreads();

            #pragma unroll
            for (int kk = 0; kk < 4; kk++) {
                unsigned a[2][4], b[4][2];
                const int ar = wm * 32 + qr;
                const int ac = kk * 8 + j;
                #pragma unroll
                for (int mt = 0; mt < 2; mt++) {
                    a[mt][0] = As[(ar + mt * 16) * 36 + ac];
                    a[mt][1] = As[(ar + mt * 16 + 8) * 36 + ac];
                    a[mt][2] = As[(ar + mt * 16) * 36 + ac + 4];
                    a[mt][3] = As[(ar + mt * 16 + 8) * 36 + ac + 4];
                }
                const int bk = kk * 8 + j;
                #pragma unroll
                for (int nt = 0; nt < 4; nt++) {
                    const int bn = wn * 32 + nt * 8 + qr;
                    b[nt][0] = Bs[bk * 72 + bn];
                    b[nt][1] = Bs[(bk + 4) * 72 + bn];
                }
                #pragma unroll
                for (int mt = 0; mt < 2; mt++)
                    #pragma unroll
                    for (int nt = 0; nt < 4; nt++)
                        mma8(acc[mt][nt], a[mt], b[nt]);
            }
        }

        // Epilogue: tf32-rounded bits (the rounding attn applied at staging).
        #pragma unroll
        for (int mt = 0; mt < 2; mt++) {
            long r0 = rowbase + wm * 32 + mt * 16 + qr;
            #pragma unroll
            for (int nt = 0; nt < 4; nt++) {
                int cc = wn * 32 + nt * 8 + 2 * j;
                *(float2*)(g_V + r0 * 64 + cc) =
                    make_float2(__uint_as_float(f2tf(acc[mt][nt][0])),
                                __uint_as_float(f2tf(acc[mt][nt][1])));
                *(float2*)(g_V + (r0 + 8) * 64 + cc) =
                    make_float2(__uint_as_float(f2tf(acc[mt][nt][2])),
                                __uint_as_float(f2tf(acc[mt][nt][3])));
            }
        }
    }
}

// ---------------------------------------------------------------------------
// Kernel 2: fused causal attention (R10 structure; staging now cp.async —
// K is bf16x2-packed in gmem, V is pre-rounded tf32 bits, so both stage as
// raw 16B copies with no register round-trip or conversion).
// ---------------------------------------------------------------------------
#define KW_ 36
#define VW_ 72
#define ATTN_SMEM_BYTES ((256 * KW_ + 256 * VW_) * 4)

__global__ __launch_bounds__(256, 2) void attn_kernel(float* __restrict__ out)
{
    extern __shared__ unsigned sm[];
    unsigned* sK = sm;
    unsigned* sV = sm + 256 * KW_;
    const unsigned sKb = scvta(sK);
    const unsigned sVb = scvta(sV);

    const int tid  = threadIdx.x;
    const int lane = tid & 31;
    const int warp = tid >> 5;
    const int j    = lane & 3;
    const int qr   = lane >> 2;

    const int bRow  = (lane & 7) + ((lane >> 4) & 1) * 8;
    const int bHalf = (lane >> 3) & 1;

    const int b = blockIdx.x;
    const unsigned* Qw = g_Qh + (long)b * T_ * H_ / 2;
    const unsigned* Kw = g_Kh + (long)b * T_ * H_ / 2;
    const float*    Vg = g_V  + (long)b * T_ * H_;
    float* ob = out + (long)b * T_ * H_;

    // Stage K and V via cp.async raw 16B copies.
    #pragma unroll
    for (int i = 0; i < 8; i++) {
        int idx = tid + i * 256;
        int r = idx >> 3, c4 = idx & 7;
        cpa16(sKb + (r * KW_ + c4 * 4) * 4, Kw + r * 32 + c4 * 4);
    }
    #pragma unroll
    for (int i = 0; i < 16; i++) {
        int idx = tid + i * 256;
        int r = idx >> 4, c4 = idx & 15;
        cpa16(sVb + (r * VW_ + c4 * 4) * 4, Vg + r * 64 + c4 * 4);
    }
    cpa_commit();
    cpa_wait0();
    __syncthreads();

    #pragma unroll 1
    for (int half = 0; half < 2; half++) {
        const int m  = (half == 0) ? warp : 15 - warp;
        const int t0 = m * 16;

        unsigned aq[4][4];
        {
            const int r = t0 + qr;
            #pragma unroll
            for (int st = 0; st < 4; st++) {
                aq[st][0] = Qw[r * 32 + st * 8 + j];
                aq[st][1] = Qw[(r + 8) * 32 + st * 8 + j];
                aq[st][2] = Qw[r * 32 + st * 8 + j + 4];
                aq[st][3] = Qw[(r + 8) * 32 + st * 8 + j + 4];
            }
        }

        float o[8][4];
        #pragma unroll
        for (int nt = 0; nt < 8; nt++)
            #pragma unroll
            for (int c = 0; c < 4; c++) o[nt][c] = 0.f;
        float rs[2] = {0.f, 0.f};

        const int nb = m / 2 + 1;
        for (int sb = 0; sb < nb; sb++) {
            const int s0 = sb * 32;

            float sacc[4][4];
            #pragma unroll
            for (int nt = 0; nt < 4; nt++)
                #pragma unroll
                for (int c = 0; c < 4; c++) sacc[nt][c] = 0.f;

            #pragma unroll
            for (int st = 0; st < 4; st++) {
                unsigned bk[4][2];
                #pragma unroll
                for (int p = 0; p < 2; p++) {
                    unsigned addr = sKb +
                        ((s0 + p * 16 + bRow) * KW_ + st * 8 + bHalf * 4) * 4;
                    ldsm4(bk[2 * p][0], bk[2 * p][1], bk[2 * p + 1][0], bk[2 * p + 1][1], addr);
                }
                #pragma unroll
                for (int nt = 0; nt < 4; nt++)
                    mma16(sacc[nt], aq[st], bk[nt]);
            }

            unsigned ap[4][4];
            const int tlo = t0 + qr, thi = tlo + 8;
            const int srcA = (lane & ~3) | (j >> 1);
            const int srcB = srcA + 2;
            const bool odd = (j & 1);
            #pragma unroll
            for (int nt = 0; nt < 4; nt++) {
                const int clo = s0 + nt * 8 + 2 * j;
                float pe0 = (clo     <= tlo) ? __expf(sacc[nt][0] * 0.0625f) : 0.f;
                float pe1 = (clo + 1 <= tlo) ? __expf(sacc[nt][1] * 0.0625f) : 0.f;
                float pe2 = (clo     <= thi) ? __expf(sacc[nt][2] * 0.0625f) : 0.f;
                float pe3 = (clo + 1 <= thi) ? __expf(sacc[nt][3] * 0.0625f) : 0.f;
                rs[0] += pe0 + pe1;
                rs[1] += pe2 + pe3;
                float g0 = __shfl_sync(0xffffffffu, pe0, srcA);
                float g1 = __shfl_sync(0xffffffffu, pe1, srcA);
                float h0 = __shfl_sync(0xffffffffu, pe0, srcB);
                float h1 = __shfl_sync(0xffffffffu, pe1, srcB);
                float g2 = __shfl_sync(0xffffffffu, pe2, srcA);
                float g3 = __shfl_sync(0xffffffffu, pe3, srcA);
                float h2 = __shfl_sync(0xffffffffu, pe2, srcB);
                float h3 = __shfl_sync(0xffffffffu, pe3, srcB);
                ap[nt][0] = f2tf(odd ? g1 : g0);
                ap[nt][1] = f2tf(odd ? g3 : g2);
                ap[nt][2] = f2tf(odd ? h1 : h0);
                ap[nt][3] = f2tf(odd ? h3 : h2);
            }

            #pragma unroll
            for (int kt = 0; kt < 4; kt++) {
                unsigned bv[8][2];
                const int sv = s0 + kt * 8 + j;
                #pragma unroll
                for (int nt = 0; nt < 8; nt++) {
                    const int hh = nt * 8 + qr;
                    bv[nt][0] = sV[sv * VW_ + hh];
                    bv[nt][1] = sV[(sv + 4) * VW_ + hh];
                }
                #pragma unroll
                for (int nt = 0; nt < 8; nt++)
                    mma8(o[nt], ap[kt], bv[nt]);
            }
        }

        #pragma unroll
        for (int h2 = 0; h2 < 2; h2++) {
            float r = rs[h2];
            r += __shfl_xor_sync(0xffffffffu, r, 1);
            r += __shfl_xor_sync(0xffffffffu, r, 2);
            rs[h2] = 1.f / r;
        }

        const int r = t0 + qr;
        #pragma unroll
        for (int nt = 0; nt < 8; nt++) {
            const int cc = nt * 8 + 2 * j;
            *(float2*)(ob + r * 64 + cc) =
                make_float2(o[nt][0] * rs[0], o[nt][1] * rs[0]);
            *(float2*)(ob + (r + 8) * 64 + cc) =
                make_float2(o[nt][2] * rs[1], o[nt][3] * rs[1]);
        }
    }
}

// ---------------------------------------------------------------------------
extern "C" void kernel_launch(void* const* d_in, const int* in_sizes, int n_in,
                              void* d_out, int out_size)
{
    const float* x  = (const float*)d_in[0];
    const float* Wq = (const float*)d_in[1];
    const float* Wk = (const float*)d_in[2];
    const float* Wv = (const float*)d_in[3];
    float* out = (float*)d_out;

    (void)in_sizes; (void)n_in; (void)out_size;

    cudaFuncSetAttribute(qkv_kernel, cudaFuncAttributeMaxDynamicSharedMemorySize,
                         QKV_SMEM_BYTES);
    cudaFuncSetAttribute(attn_kernel, cudaFuncAttributeMaxDynamicSharedMemorySize,
                         ATTN_SMEM_BYTES);

    prep_kernel<<<64, 256>>>(Wq, Wk);
    qkv_kernel<<<dim3(2, (B_ * T_) / 128), 256, QKV_SMEM_BYTES>>>(x, Wv);
    attn_kernel<<<B_, 256, ATTN_SMEM_BYTES>>>(out);
}